// round 6
// baseline (speedup 1.0000x reference)
#include <cuda_runtime.h>
#include <cuda_bf16.h>
#include <cstdint>

// ---------------------------------------------------------------------------
// RegionModel round-6: implicit-GEMM conv on the classic tensor-core path
// (mma.sync.m16n8k16 bf16, legal on plain sm_103 target) with split-bf16
// 3-term fp32 emulation folded into the K dimension:
//   K' = 3*CIN*9, segments [a_hi*b_hi | a_lo*b_hi | a_hi*b_lo]
// Per conv layer, per sample: D[128px, COUT] = A[128, K'] * B[COUT, K']^T.
// A staged in smem by im2col (table-driven), B copied from pre-expanded
// per-region bf16 weight images. fp32 accumulators, bias+ReLU epilogue, NHWC.
// ---------------------------------------------------------------------------

#define B_ 128
#define R_ 8

typedef unsigned int u32;

// Scratch (device globals: allocation-guard safe). Activations NHWC fp32.
__device__ float g_buf1[(size_t)B_ * 128 * 128 * 32];   // 256 MiB
__device__ float g_buf2[(size_t)B_ * 64 * 64 * 64];     // 128 MiB
__device__ float g_buf3[(size_t)B_ * 32 * 32 * 128];    //  64 MiB
__device__ float g_part[B_ * 8 * 128];
// Weight images: [R][NC][COUT][72] bf16, K'-chunked, zero-padded
__device__ __align__(16) __nv_bfloat16 g_w1img[R_ * 2 * 32 * 72];
__device__ __align__(16) __nv_bfloat16 g_w2img[R_ * 14 * 64 * 72];
__device__ __align__(16) __nv_bfloat16 g_w3img[R_ * 27 * 128 * 72];

// ---------------------------------------------------------------------------
// Weight prep: W[R,COUT,CIN,3,3] fp32 -> split-bf16 chunk images.
// k' = term*(CIN*9) + tap*CIN + ci ; B value: term 0,1 -> hi, term 2 -> lo.
// ---------------------------------------------------------------------------
template <int CIN, int COUT, int KP>
__global__ void __launch_bounds__(256) prep_w(const float* __restrict__ W,
                                              __nv_bfloat16* __restrict__ img)
{
    constexpr int NC = (KP + 63) / 64;
    const int idx = blockIdx.x * 256 + threadIdx.x;
    const int total = R_ * NC * COUT * 72;
    if (idx >= total) return;
    const int kl = idx % 72;
    int t = idx / 72;
    const int n = t % COUT; t /= COUT;
    const int c = t % NC;
    const int r = t / NC;

    __nv_bfloat16 ob = __float2bfloat16_rn(0.0f);
    const int kq = c * 64 + kl;
    if (kl < 64 && kq < KP) {
        const int term = kq / (CIN * 9);
        const int kg   = kq - term * (CIN * 9);
        const int tap  = kg / CIN;
        const int ci   = kg - tap * CIN;
        const float w  = W[(((size_t)r * COUT + n) * CIN + ci) * 9 + tap];
        const __nv_bfloat16 h = __float2bfloat16_rn(w);
        ob = (term == 2) ? __float2bfloat16_rn(w - __bfloat162float(h)) : h;
    }
    img[idx] = ob;
}

// ---------------------------------------------------------------------------
// Implicit-GEMM conv. grid = (HOUT*HOUT/128, 1, B). 256 threads (8 warps).
// Each warp owns a 16-row (pixel) strip; NT = COUT/8 n-tiles.
// ---------------------------------------------------------------------------
template <int CIN, int COUT, int HOUT, int KP, bool IS_NCHW>
__global__ void __launch_bounds__(256) conv_mma_k(
    const float* __restrict__ in, const __nv_bfloat16* __restrict__ wimg,
    const float* __restrict__ Bias, const int* __restrict__ region,
    float* __restrict__ out)
{
    constexpr int HIN  = 2 * HOUT;
    constexpr int NC   = (KP + 63) / 64;
    constexpr int NT   = COUT / 8;
    constexpr int LOGH = (HOUT == 128) ? 7 : (HOUT == 64) ? 6 : 5;

    __shared__ __nv_bfloat16 As[128 * 72];     // 144B pitch
    __shared__ __nv_bfloat16 Bs[COUT * 72];
    __shared__ float bias_s[COUT];
    __shared__ u32 ktab[NC * 64];

    const int tid = threadIdx.x, lane = tid & 31, wid = tid >> 5;
    const int b   = blockIdx.z;
    const int px0 = blockIdx.x * 128;
    const int r   = region[b] & (R_ - 1);

    // k' lookup tables (once) + bias
    for (int i = tid; i < NC * 64; i += 256) {
        u32 v;
        if (i < KP) {
            const int term = i / (CIN * 9);
            const int kg   = i - term * (CIN * 9);
            const int tap  = kg / CIN;
            const int ci   = kg - tap * CIN;
            const u32 sel  = (term == 1) ? 1u : 0u;   // A: seg1 -> lo
            v = (u32)ci | ((u32)(tap / 3) << 16) | ((u32)(tap % 3) << 20) | (sel << 24);
        } else {
            v = 2u << 24;                              // zero element
        }
        ktab[i] = v;
    }
    for (int i = tid; i < COUT; i += 256) bias_s[i] = Bias[r * COUT + i];

    float acc[NT][4];
#pragma unroll
    for (int n = 0; n < NT; n++) {
        acc[n][0] = acc[n][1] = acc[n][2] = acc[n][3] = 0.0f;
    }

    const __nv_bfloat16* wr = wimg + (size_t)r * NC * COUT * 72;
    const int g  = lane >> 2;
    const int tc = lane & 3;

    __syncthreads();

    for (int c = 0; c < NC; c++) {
        // ---- stage B: pure copy, COUT rows x 144B = COUT*9 uint4 ----
        {
            const uint4* s4 = (const uint4*)(wr + (size_t)c * COUT * 72);
            uint4* d4 = (uint4*)Bs;
            for (int i = tid; i < COUT * 9; i += 256) d4[i] = s4[i];
        }
        // ---- stage A: im2col gather + split-bf16 (table-driven) ----
        for (int idx = tid; idx < 4096; idx += 256) {
            const int m  = idx >> 5;
            const int kp = idx & 31;
            const int px = px0 + m;
            const int oy = px >> LOGH, ox = px & (HOUT - 1);
            u32 w2 = 0;
#pragma unroll
            for (int j = 0; j < 2; j++) {
                const u32 tb  = ktab[c * 64 + kp * 2 + j];
                const u32 sel = tb >> 24;
                float x = 0.0f;
                if (sel != 2u) {
                    const int ci = tb & 0xFFFF;
                    const int iy = 2 * oy + ((tb >> 16) & 0xF) - 1;
                    const int ix = 2 * ox + ((tb >> 20) & 0xF) - 1;
                    if ((unsigned)iy < (unsigned)HIN && (unsigned)ix < (unsigned)HIN) {
                        x = IS_NCHW
                          ? __ldg(in + ((size_t)(b * CIN + ci) * HIN + iy) * HIN + ix)
                          : __ldg(in + (((size_t)b * HIN + iy) * HIN + ix) * CIN + ci);
                    }
                }
                const __nv_bfloat16 h = __float2bfloat16_rn(x);
                const __nv_bfloat16 val =
                    (sel == 1u) ? __float2bfloat16_rn(x - __bfloat162float(h)) : h;
                w2 |= (u32)__bfloat16_as_ushort(val) << (16 * j);
            }
            *(u32*)((char*)As + m * 144 + kp * 4) = w2;
        }
        __syncthreads();

        // ---- compute: 4 k-steps of 16, NT n-tiles ----
        const char* arow = (const char*)As + (wid * 16 + g) * 144 + tc * 4;
        const char* brow = (const char*)Bs + g * 144 + tc * 4;
#pragma unroll
        for (int ks = 0; ks < 4; ks++) {
            const int kb = ks * 32;                       // 16 bf16 = 32 bytes
            const u32 a0 = *(const u32*)(arow + kb);
            const u32 a1 = *(const u32*)(arow + 8 * 144 + kb);
            const u32 a2 = *(const u32*)(arow + kb + 16);
            const u32 a3 = *(const u32*)(arow + 8 * 144 + kb + 16);
#pragma unroll
            for (int nt = 0; nt < NT; nt++) {
                const u32 b0 = *(const u32*)(brow + nt * 8 * 144 + kb);
                const u32 b1 = *(const u32*)(brow + nt * 8 * 144 + kb + 16);
                asm volatile(
                    "mma.sync.aligned.m16n8k16.row.col.f32.bf16.bf16.f32 "
                    "{%0,%1,%2,%3}, {%4,%5,%6,%7}, {%8,%9}, {%0,%1,%2,%3};"
                    : "+f"(acc[nt][0]), "+f"(acc[nt][1]),
                      "+f"(acc[nt][2]), "+f"(acc[nt][3])
                    : "r"(a0), "r"(a1), "r"(a2), "r"(a3), "r"(b0), "r"(b1));
            }
        }
        __syncthreads();
    }

    // ---- epilogue: bias + ReLU -> NHWC fp32 ----
#pragma unroll
    for (int half = 0; half < 2; half++) {
        const int m  = wid * 16 + g + half * 8;
        const int px = px0 + m;
        const int oy = px >> LOGH, ox = px & (HOUT - 1);
        float* op = out + (((size_t)b * HOUT + oy) * HOUT + ox) * COUT;
#pragma unroll
        for (int nt = 0; nt < NT; nt++) {
            const int n = nt * 8 + tc * 2;
            float2 v;
            v.x = fmaxf(acc[nt][half * 2 + 0] + bias_s[n + 0], 0.0f);
            v.y = fmaxf(acc[nt][half * 2 + 1] + bias_s[n + 1], 0.0f);
            *(float2*)(op + n) = v;
        }
    }
}

// ---------------------------------------------------------------------------
// GAP partials: NHWC [B,32,32,128], each block sums a 128-px slab.
// ---------------------------------------------------------------------------
__global__ void __launch_bounds__(128) gap_part(const float* __restrict__ in,
                                                float* __restrict__ part)
{
    const int b = blockIdx.y, s = blockIdx.x, c = threadIdx.x;
    const float* p = in + ((size_t)b * 1024 + s * 128) * 128 + c;
    float a0 = 0, a1 = 0, a2 = 0, a3 = 0;
#pragma unroll 4
    for (int i = 0; i < 128; i += 4) {
        a0 += p[(size_t)(i + 0) * 128];
        a1 += p[(size_t)(i + 1) * 128];
        a2 += p[(size_t)(i + 2) * 128];
        a3 += p[(size_t)(i + 3) * 128];
    }
    part[(b * 8 + s) * 128 + c] = a0 + a1 + a2 + a3;
}

// ---------------------------------------------------------------------------
// FC (reduces GAP partials): one block of 128 threads per sample.
// ---------------------------------------------------------------------------
__global__ void __launch_bounds__(128) fc_k(const float* __restrict__ part,
                                            const float* __restrict__ fw,
                                            const float* __restrict__ fb,
                                            const int* __restrict__ region,
                                            float* __restrict__ out)
{
    __shared__ float f[128];
    const int b = blockIdx.x, tid = threadIdx.x;
    const int r = region[b] & (R_ - 1);
    float s = 0.0f;
#pragma unroll
    for (int q = 0; q < 8; q++) s += part[(b * 8 + q) * 128 + tid];
    f[tid] = s * (1.0f / 1024.0f);
    __syncthreads();
    if (tid < 32) {
        const float* w0 = fw + ((size_t)r * 2 + 0) * 128;
        const float* w1 = fw + ((size_t)r * 2 + 1) * 128;
        float p0 = 0.0f, p1 = 0.0f;
#pragma unroll
        for (int i = tid; i < 128; i += 32) {
            p0 = fmaf(f[i], w0[i], p0);
            p1 = fmaf(f[i], w1[i], p1);
        }
#pragma unroll
        for (int o = 16; o > 0; o >>= 1) {
            p0 += __shfl_down_sync(0xFFFFFFFFu, p0, o);
            p1 += __shfl_down_sync(0xFFFFFFFFu, p1, o);
        }
        if (tid == 0) {
            out[b * 2 + 0] = p0 + fb[r * 2 + 0];
            out[b * 2 + 1] = p1 + fb[r * 2 + 1];
        }
    }
}

// ---------------------------------------------------------------------------
extern "C" void kernel_launch(void* const* d_in, const int* in_sizes, int n_in,
                              void* d_out, int out_size)
{
    const float* image  = (const float*)d_in[0];
    const int*   region = (const int*)d_in[1];
    const float* w1     = (const float*)d_in[2];
    const float* b1     = (const float*)d_in[3];
    const float* w2     = (const float*)d_in[4];
    const float* b2     = (const float*)d_in[5];
    const float* w3     = (const float*)d_in[6];
    const float* b3     = (const float*)d_in[7];
    const float* fw     = (const float*)d_in[8];
    const float* fb     = (const float*)d_in[9];
    float* out = (float*)d_out;

    float *buf1, *buf2, *buf3, *part;
    __nv_bfloat16 *w1img, *w2img, *w3img;
    cudaGetSymbolAddress((void**)&buf1, g_buf1);
    cudaGetSymbolAddress((void**)&buf2, g_buf2);
    cudaGetSymbolAddress((void**)&buf3, g_buf3);
    cudaGetSymbolAddress((void**)&part, g_part);
    cudaGetSymbolAddress((void**)&w1img, g_w1img);
    cudaGetSymbolAddress((void**)&w2img, g_w2img);
    cudaGetSymbolAddress((void**)&w3img, g_w3img);

    // Weight prep (runs every launch; deterministic)
    prep_w<3, 32, 81><<<(R_ * 2 * 32 * 72 + 255) / 256, 256>>>(w1, w1img);
    prep_w<32, 64, 864><<<(R_ * 14 * 64 * 72 + 255) / 256, 256>>>(w2, w2img);
    prep_w<64, 128, 1728><<<(R_ * 27 * 128 * 72 + 255) / 256, 256>>>(w3, w3img);

    // conv1: 3->32, 16384 px -> 128 tiles
    conv_mma_k<3, 32, 128, 81, true><<<dim3(128, 1, B_), 256>>>(
        image, w1img, b1, region, buf1);
    // conv2: 32->64, 4096 px -> 32 tiles
    conv_mma_k<32, 64, 64, 864, false><<<dim3(32, 1, B_), 256>>>(
        buf1, w2img, b2, region, buf2);
    // conv3: 64->128, 1024 px -> 8 tiles
    conv_mma_k<64, 128, 32, 1728, false><<<dim3(8, 1, B_), 256>>>(
        buf2, w3img, b3, region, buf3);

    gap_part<<<dim3(8, B_), 128>>>(buf3, part);
    fc_k<<<B_, 128>>>(part, fw, fb, region, out);
}

// round 7
// speedup vs baseline: 2.8136x; 2.8136x over previous
#include <cuda_runtime.h>
#include <cuda_bf16.h>
#include <cstdint>

// ---------------------------------------------------------------------------
// RegionModel round-7: mma.sync bf16 implicit GEMM, split-bf16 3-term fp32
// emulation with SEPARATE hi/lo operand tiles (terms: Ah*Bh + Ah*Bl + Al*Bh).
// Activations flow between conv layers as NHWC bf16 hi/lo planes, so im2col
// staging is a pure u64 copy (no converts, shift-only index math).
// conv3 emits fp32 NHWC for GAP/FC.
// ---------------------------------------------------------------------------

#define B_ 128
#define R_ 8

typedef unsigned int u32;
typedef unsigned long long u64;
typedef unsigned short u16;

// Activations (device globals)
__device__ __align__(16) __nv_bfloat16 g_b1h[(size_t)B_ * 128 * 128 * 32];
__device__ __align__(16) __nv_bfloat16 g_b1l[(size_t)B_ * 128 * 128 * 32];
__device__ __align__(16) __nv_bfloat16 g_b2h[(size_t)B_ * 64 * 64 * 64];
__device__ __align__(16) __nv_bfloat16 g_b2l[(size_t)B_ * 64 * 64 * 64];
__device__ float g_buf3[(size_t)B_ * 32 * 32 * 128];
__device__ float g_part[B_ * 8 * 128];
// Weight images: [R][NC][hi|lo][COUT][72 u16], k = tap*CIN + ci, zero-padded
__device__ __align__(16) __nv_bfloat16 g_w1img[R_ * 1 * 2 * 32 * 72];
__device__ __align__(16) __nv_bfloat16 g_w2img[R_ * 5 * 2 * 64 * 72];
__device__ __align__(16) __nv_bfloat16 g_w3img[R_ * 9 * 2 * 128 * 72];

// ---------------------------------------------------------------------------
template <int CIN, int COUT>
__global__ void __launch_bounds__(256) prep_w(const float* __restrict__ W,
                                              __nv_bfloat16* __restrict__ img)
{
    constexpr int K  = CIN * 9;
    constexpr int NC = (K + 63) / 64;
    const int idx = blockIdx.x * 256 + threadIdx.x;
    if (idx >= R_ * NC * 2 * COUT * 72) return;
    const int kl = idx % 72;
    int t = idx / 72;
    const int n  = t % COUT; t /= COUT;
    const int hl = t % 2;    t /= 2;
    const int c  = t % NC;
    const int r  = t / NC;

    __nv_bfloat16 ob = __float2bfloat16_rn(0.0f);
    const int k = c * 64 + kl;
    if (kl < 64 && k < K) {
        const int tap = k / CIN, ci = k - tap * CIN;
        const float w = W[(((size_t)r * COUT + n) * CIN + ci) * 9 + tap];
        const __nv_bfloat16 h = __float2bfloat16_rn(w);
        ob = hl ? __float2bfloat16_rn(w - __bfloat162float(h)) : h;
    }
    img[idx] = ob;
}

// ---------------------------------------------------------------------------
// Implicit-GEMM conv. grid = (HOUT*HOUT/128, 1, B). 256 threads, 8 warps.
// Smem: Ash[128*72] | Asl[128*72] | Bs[2*COUT*72] | bias[COUT]  (u16 pitch 72)
// ---------------------------------------------------------------------------
template <int CIN, int COUT, int HOUT, bool FIRST, bool OUTF32>
__global__ void __launch_bounds__(256) conv_mma2(
    const float* __restrict__ img,                 // FIRST: fp32 NCHW input
    const __nv_bfloat16* __restrict__ src_h,
    const __nv_bfloat16* __restrict__ src_l,       // !FIRST: bf16 NHWC planes
    const __nv_bfloat16* __restrict__ wimg,
    const float* __restrict__ Bias, const int* __restrict__ region,
    float* __restrict__ outf,
    __nv_bfloat16* __restrict__ out_h, __nv_bfloat16* __restrict__ out_l)
{
    constexpr int HIN  = 2 * HOUT;
    constexpr int K    = CIN * 9;
    constexpr int NC   = (K + 63) / 64;
    constexpr int NT   = COUT / 8;
    constexpr int LOGH = (HOUT == 128) ? 7 : (HOUT == 64) ? 6 : 5;
    constexpr int LOGC = (CIN == 64) ? 6 : 5;            // !FIRST only

    extern __shared__ __align__(16) char sm[];
    __nv_bfloat16* Ash = (__nv_bfloat16*)sm;             // 128*72
    __nv_bfloat16* Asl = Ash + 128 * 72;
    __nv_bfloat16* Bs  = Asl + 128 * 72;                 // hi[COUT*72] lo[COUT*72]
    float* bias_s      = (float*)(Bs + 2 * COUT * 72);

    const int tid = threadIdx.x, lane = tid & 31, wid = tid >> 5;
    const int b   = blockIdx.z;
    const int px0 = blockIdx.x * 128;
    const int r   = region[b] & (R_ - 1);
    const int g   = lane >> 2, tc = lane & 3;

    for (int i = tid; i < COUT; i += 256) bias_s[i] = Bias[r * COUT + i];

    float acc[NT][4];
#pragma unroll
    for (int n = 0; n < NT; n++)
        acc[n][0] = acc[n][1] = acc[n][2] = acc[n][3] = 0.0f;

    const __nv_bfloat16* wr = wimg + (size_t)r * NC * 2 * COUT * 72;

    for (int c = 0; c < NC; c++) {
        __syncthreads();
        // ---- stage B: uint4 copy of pre-split chunk image (hi + lo) ----
        {
            const uint4* s4 = (const uint4*)(wr + (size_t)c * 2 * COUT * 72);
            uint4* d4 = (uint4*)Bs;
            for (int i = tid; i < 2 * COUT * 9; i += 256) d4[i] = s4[i];
        }
        // ---- stage A ----
        if (FIRST) {
            // CIN=3: u16 elements with inline fp32 split; k padded to 32
            for (int i = tid; i < 128 * 32; i += 256) {
                const int m = i >> 5, k = i & 31;
                const int px = px0 + m;
                const int oy = px >> LOGH, ox = px & (HOUT - 1);
                float x = 0.0f;
                if (k < 27) {
                    const int tap = k / 3, ci = k - 3 * tap;
                    const int ty = tap / 3, tx = tap - 3 * ty;
                    const int iy = 2 * oy + ty - 1, ix = 2 * ox + tx - 1;
                    if ((unsigned)iy < (unsigned)HIN && (unsigned)ix < (unsigned)HIN)
                        x = __ldg(img + ((size_t)(b * 3 + ci) * HIN + iy) * HIN + ix);
                }
                const __nv_bfloat16 h = __float2bfloat16_rn(x);
                Ash[m * 72 + k] = h;
                Asl[m * 72 + k] = __float2bfloat16_rn(x - __bfloat162float(h));
            }
        } else {
            // u64 copy: 4 channels per op, shift-only index math
            for (int i = tid; i < 128 * 16; i += 256) {
                const int m = i >> 4, q = i & 15;
                const int k = c * 64 + q * 4;
                const int px = px0 + m;
                const int oy = px >> LOGH, ox = px & (HOUT - 1);
                u64 h = 0, l = 0;
                if (k < K) {
                    const int tap = k >> LOGC, ci = k & (CIN - 1);
                    const int ty = tap / 3, tx = tap - 3 * ty;
                    const int iy = 2 * oy + ty - 1, ix = 2 * ox + tx - 1;
                    if ((unsigned)iy < (unsigned)HIN && (unsigned)ix < (unsigned)HIN) {
                        const size_t off =
                            ((size_t)(b * HIN + iy) * HIN + ix) * CIN + ci;
                        h = *(const u64*)(src_h + off);
                        l = *(const u64*)(src_l + off);
                    }
                }
                *(u64*)((char*)Ash + m * 144 + q * 8) = h;
                *(u64*)((char*)Asl + m * 144 + q * 8) = l;
            }
        }
        __syncthreads();

        // ---- MMA: 3 terms (Ah*Bh, Ah*Bl, Al*Bh) ----
        const int nks = FIRST ? 2 : ((K - c * 64 >= 64) ? 4 : 2);
        const char* ah = (const char*)Ash + (wid * 16 + g) * 144 + tc * 4;
        const char* al = (const char*)Asl + (wid * 16 + g) * 144 + tc * 4;
        const char* bh = (const char*)Bs + g * 144 + tc * 4;
        const char* bl = bh + COUT * 144;
#pragma unroll
        for (int term = 0; term < 3; term++) {
            const char* arow = (term == 2) ? al : ah;
            const char* brow = (term == 1) ? bl : bh;
            for (int ks = 0; ks < nks; ks++) {
                const int kb = ks * 32;
                const u32 a0 = *(const u32*)(arow + kb);
                const u32 a1 = *(const u32*)(arow + 8 * 144 + kb);
                const u32 a2 = *(const u32*)(arow + kb + 16);
                const u32 a3 = *(const u32*)(arow + 8 * 144 + kb + 16);
#pragma unroll
                for (int nt = 0; nt < NT; nt++) {
                    const u32 b0 = *(const u32*)(brow + nt * 8 * 144 + kb);
                    const u32 b1 = *(const u32*)(brow + nt * 8 * 144 + kb + 16);
                    asm volatile(
                        "mma.sync.aligned.m16n8k16.row.col.f32.bf16.bf16.f32 "
                        "{%0,%1,%2,%3}, {%4,%5,%6,%7}, {%8,%9}, {%0,%1,%2,%3};"
                        : "+f"(acc[nt][0]), "+f"(acc[nt][1]),
                          "+f"(acc[nt][2]), "+f"(acc[nt][3])
                        : "r"(a0), "r"(a1), "r"(a2), "r"(a3), "r"(b0), "r"(b1));
                }
            }
        }
    }

    // ---- epilogue: bias + ReLU ----
#pragma unroll
    for (int half = 0; half < 2; half++) {
        const int m  = wid * 16 + g + half * 8;
        const int px = px0 + m;
        const int oy = px >> LOGH, ox = px & (HOUT - 1);
        const size_t base = (((size_t)b * HOUT + oy) * HOUT + ox) * COUT;
#pragma unroll
        for (int nt = 0; nt < NT; nt++) {
            const int n = nt * 8 + tc * 2;
            const float y0 = fmaxf(acc[nt][half * 2 + 0] + bias_s[n + 0], 0.0f);
            const float y1 = fmaxf(acc[nt][half * 2 + 1] + bias_s[n + 1], 0.0f);
            if (OUTF32) {
                *(float2*)(outf + base + n) = make_float2(y0, y1);
            } else {
                const __nv_bfloat16 h0 = __float2bfloat16_rn(y0);
                const __nv_bfloat16 h1 = __float2bfloat16_rn(y1);
                const __nv_bfloat16 l0 = __float2bfloat16_rn(y0 - __bfloat162float(h0));
                const __nv_bfloat16 l1 = __float2bfloat16_rn(y1 - __bfloat162float(h1));
                *(u32*)(out_h + base + n) =
                    (u32)__bfloat16_as_ushort(h0) | ((u32)__bfloat16_as_ushort(h1) << 16);
                *(u32*)(out_l + base + n) =
                    (u32)__bfloat16_as_ushort(l0) | ((u32)__bfloat16_as_ushort(l1) << 16);
            }
        }
    }
}

// ---------------------------------------------------------------------------
__global__ void __launch_bounds__(128) gap_part(const float* __restrict__ in,
                                                float* __restrict__ part)
{
    const int b = blockIdx.y, s = blockIdx.x, c = threadIdx.x;
    const float* p = in + ((size_t)b * 1024 + s * 128) * 128 + c;
    float a0 = 0, a1 = 0, a2 = 0, a3 = 0;
#pragma unroll 4
    for (int i = 0; i < 128; i += 4) {
        a0 += p[(size_t)(i + 0) * 128];
        a1 += p[(size_t)(i + 1) * 128];
        a2 += p[(size_t)(i + 2) * 128];
        a3 += p[(size_t)(i + 3) * 128];
    }
    part[(b * 8 + s) * 128 + c] = a0 + a1 + a2 + a3;
}

__global__ void __launch_bounds__(128) fc_k(const float* __restrict__ part,
                                            const float* __restrict__ fw,
                                            const float* __restrict__ fb,
                                            const int* __restrict__ region,
                                            float* __restrict__ out)
{
    __shared__ float f[128];
    const int b = blockIdx.x, tid = threadIdx.x;
    const int r = region[b] & (R_ - 1);
    float s = 0.0f;
#pragma unroll
    for (int q = 0; q < 8; q++) s += part[(b * 8 + q) * 128 + tid];
    f[tid] = s * (1.0f / 1024.0f);
    __syncthreads();
    if (tid < 32) {
        const float* w0 = fw + ((size_t)r * 2 + 0) * 128;
        const float* w1 = fw + ((size_t)r * 2 + 1) * 128;
        float p0 = 0.0f, p1 = 0.0f;
#pragma unroll
        for (int i = tid; i < 128; i += 32) {
            p0 = fmaf(f[i], w0[i], p0);
            p1 = fmaf(f[i], w1[i], p1);
        }
#pragma unroll
        for (int o = 16; o > 0; o >>= 1) {
            p0 += __shfl_down_sync(0xFFFFFFFFu, p0, o);
            p1 += __shfl_down_sync(0xFFFFFFFFu, p1, o);
        }
        if (tid == 0) {
            out[b * 2 + 0] = p0 + fb[r * 2 + 0];
            out[b * 2 + 1] = p1 + fb[r * 2 + 1];
        }
    }
}

// ---------------------------------------------------------------------------
extern "C" void kernel_launch(void* const* d_in, const int* in_sizes, int n_in,
                              void* d_out, int out_size)
{
    const float* image  = (const float*)d_in[0];
    const int*   region = (const int*)d_in[1];
    const float* w1     = (const float*)d_in[2];
    const float* b1     = (const float*)d_in[3];
    const float* w2     = (const float*)d_in[4];
    const float* b2     = (const float*)d_in[5];
    const float* w3     = (const float*)d_in[6];
    const float* b3     = (const float*)d_in[7];
    const float* fw     = (const float*)d_in[8];
    const float* fb     = (const float*)d_in[9];
    float* out = (float*)d_out;

    __nv_bfloat16 *b1h, *b1l, *b2h, *b2l, *w1img, *w2img, *w3img;
    float *buf3, *part;
    cudaGetSymbolAddress((void**)&b1h, g_b1h);
    cudaGetSymbolAddress((void**)&b1l, g_b1l);
    cudaGetSymbolAddress((void**)&b2h, g_b2h);
    cudaGetSymbolAddress((void**)&b2l, g_b2l);
    cudaGetSymbolAddress((void**)&buf3, g_buf3);
    cudaGetSymbolAddress((void**)&part, g_part);
    cudaGetSymbolAddress((void**)&w1img, g_w1img);
    cudaGetSymbolAddress((void**)&w2img, g_w2img);
    cudaGetSymbolAddress((void**)&w3img, g_w3img);

    // Weight prep
    prep_w<3, 32><<<(R_ * 1 * 2 * 32 * 72 + 255) / 256, 256>>>(w1, w1img);
    prep_w<32, 64><<<(R_ * 5 * 2 * 64 * 72 + 255) / 256, 256>>>(w2, w2img);
    prep_w<64, 128><<<(R_ * 9 * 2 * 128 * 72 + 255) / 256, 256>>>(w3, w3img);

    // Dynamic smem sizes: A(2*18432 B) + B(2*COUT*144 B) + bias
    const int SM1 = 36864 + 2 * 32 * 144 + 32 * 4;     // 46 KB
    const int SM2 = 36864 + 2 * 64 * 144 + 64 * 4;     // 55 KB
    const int SM3 = 36864 + 2 * 128 * 144 + 128 * 4;   // 74 KB
    cudaFuncSetAttribute(conv_mma2<3, 32, 128, true, false>,
                         cudaFuncAttributeMaxDynamicSharedMemorySize, SM1);
    cudaFuncSetAttribute(conv_mma2<32, 64, 64, false, false>,
                         cudaFuncAttributeMaxDynamicSharedMemorySize, SM2);
    cudaFuncSetAttribute(conv_mma2<64, 128, 32, false, true>,
                         cudaFuncAttributeMaxDynamicSharedMemorySize, SM3);

    // conv1: fp32 NCHW image -> bf16 hi/lo NHWC
    conv_mma2<3, 32, 128, true, false><<<dim3(128, 1, B_), 256, SM1>>>(
        image, nullptr, nullptr, w1img, b1, region, nullptr, b1h, b1l);
    // conv2: bf16 planes -> bf16 planes
    conv_mma2<32, 64, 64, false, false><<<dim3(32, 1, B_), 256, SM2>>>(
        nullptr, b1h, b1l, w2img, b2, region, nullptr, b2h, b2l);
    // conv3: bf16 planes -> fp32 NHWC
    conv_mma2<64, 128, 32, false, true><<<dim3(8, 1, B_), 256, SM3>>>(
        nullptr, b2h, b2l, w3img, b3, region, buf3, nullptr, nullptr);

    gap_part<<<dim3(8, B_), 128>>>(buf3, part);
    fc_k<<<B_, 128>>>(part, fw, fb, region, out);
}

// round 8
// speedup vs baseline: 3.4047x; 1.2101x over previous
#include <cuda_runtime.h>
#include <cuda_bf16.h>
#include <cstdint>

// ---------------------------------------------------------------------------
// RegionModel round-8: mma.sync bf16 implicit GEMM, split-bf16 3-term fp32
// emulation (Ah*Bh + Ah*Bl + Al*Bh). All activations (incl. the input image,
// pre-split by prep_img into padded 4-ch planes) live as NHWC bf16 hi/lo
// planes, so im2col staging for EVERY conv is a pure cp.async u64 copy with
// zero-fill for halos. K-chunks double-buffered (STAGES=2) for conv2/conv3.
// ---------------------------------------------------------------------------

#define B_ 128
#define R_ 8

typedef unsigned int u32;
typedef unsigned long long u64;
typedef unsigned short u16;

// Activations (device globals)
__device__ __align__(16) __nv_bfloat16 g_imgh[(size_t)B_ * 256 * 256 * 4];
__device__ __align__(16) __nv_bfloat16 g_imgl[(size_t)B_ * 256 * 256 * 4];
__device__ __align__(16) __nv_bfloat16 g_b1h[(size_t)B_ * 128 * 128 * 32];
__device__ __align__(16) __nv_bfloat16 g_b1l[(size_t)B_ * 128 * 128 * 32];
__device__ __align__(16) __nv_bfloat16 g_b2h[(size_t)B_ * 64 * 64 * 64];
__device__ __align__(16) __nv_bfloat16 g_b2l[(size_t)B_ * 64 * 64 * 64];
__device__ float g_buf3[(size_t)B_ * 32 * 32 * 128];
__device__ float g_part[B_ * 8 * 128];
// Weight images: [R][NC][hi|lo][COUT][72 u16], k = tap*CINP + ci, zero-padded
__device__ __align__(16) __nv_bfloat16 g_w1img[R_ * 1 * 2 * 32 * 72];
__device__ __align__(16) __nv_bfloat16 g_w2img[R_ * 5 * 2 * 64 * 72];
__device__ __align__(16) __nv_bfloat16 g_w3img[R_ * 9 * 2 * 128 * 72];

__device__ __forceinline__ u32 smem_u32(const void* p) {
    u32 a;
    asm("{ .reg .u64 t; cvta.to.shared.u64 t, %1; cvt.u32.u64 %0, t; }"
        : "=r"(a) : "l"(p));
    return a;
}
#define CP16(dst, src) \
    asm volatile("cp.async.cg.shared.global [%0], [%1], 16;" :: "r"(dst), "l"(src))
#define CP8Z(dst, src, sz) \
    asm volatile("cp.async.ca.shared.global [%0], [%1], 8, %2;" \
                 :: "r"(dst), "l"(src), "r"(sz))
#define CP_COMMIT() asm volatile("cp.async.commit_group;" ::: "memory")
#define CP_WAIT0()  asm volatile("cp.async.wait_group 0;" ::: "memory")
#define CP_WAIT1()  asm volatile("cp.async.wait_group 1;" ::: "memory")

// ---------------------------------------------------------------------------
// Image pre-split: fp32 NCHW [B,3,256,256] -> bf16 hi/lo NHWC4 (ch3 = 0)
// ---------------------------------------------------------------------------
__global__ void __launch_bounds__(256) prep_img(const float* __restrict__ img,
                                                __nv_bfloat16* __restrict__ oh,
                                                __nv_bfloat16* __restrict__ ol)
{
    const int idx = blockIdx.x * 256 + threadIdx.x;   // B*65536
    if (idx >= B_ * 65536) return;
    const int b = idx >> 16, p = idx & 65535;
    const float* ip = img + (size_t)b * 3 * 65536 + p;
    u16 h[4], l[4];
#pragma unroll
    for (int c = 0; c < 3; c++) {
        const float x = __ldg(ip + (size_t)c * 65536);
        const __nv_bfloat16 hb = __float2bfloat16_rn(x);
        h[c] = __bfloat16_as_ushort(hb);
        l[c] = __bfloat16_as_ushort(__float2bfloat16_rn(x - __bfloat162float(hb)));
    }
    h[3] = 0; l[3] = 0;
    ((u64*)oh)[idx] = *(const u64*)h;
    ((u64*)ol)[idx] = *(const u64*)l;
}

// ---------------------------------------------------------------------------
// Weight prep: W[R,COUT,CIN,3,3] fp32 -> hi/lo chunk images, k = tap*CINP+ci
// ---------------------------------------------------------------------------
template <int CIN, int CINP, int COUT>
__global__ void __launch_bounds__(256) prep_w(const float* __restrict__ W,
                                              __nv_bfloat16* __restrict__ img)
{
    constexpr int KP = 9 * CINP;
    constexpr int NC = (KP + 63) / 64;
    const int idx = blockIdx.x * 256 + threadIdx.x;
    if (idx >= R_ * NC * 2 * COUT * 72) return;
    const int kl = idx % 72;
    int t = idx / 72;
    const int n  = t % COUT; t /= COUT;
    const int hl = t % 2;    t /= 2;
    const int c  = t % NC;
    const int r  = t / NC;

    __nv_bfloat16 ob = __float2bfloat16_rn(0.0f);
    const int k = c * 64 + kl;
    if (kl < 64 && k < KP) {
        const int tap = k / CINP, ci = k % CINP;
        if (tap < 9 && ci < CIN) {
            const float w = W[(((size_t)r * COUT + n) * CIN + ci) * 9 + tap];
            const __nv_bfloat16 h = __float2bfloat16_rn(w);
            ob = hl ? __float2bfloat16_rn(w - __bfloat162float(h)) : h;
        }
    }
    img[idx] = ob;
}

// ---------------------------------------------------------------------------
// Implicit-GEMM conv. grid = (HOUT*HOUT/128, 1, B). 256 threads, 8 warps.
// Per stage: Ash[128*72] | Asl[128*72] | Bs hi/lo [2*COUT*72]  (u16, pitch 72)
// ---------------------------------------------------------------------------
template <int CINP, int LOGC, int COUT, int HOUT, bool OUTF32, int STAGES>
__global__ void __launch_bounds__(256) conv_mma3(
    const __nv_bfloat16* __restrict__ src_h, const __nv_bfloat16* __restrict__ src_l,
    const __nv_bfloat16* __restrict__ wimg, const float* __restrict__ Bias,
    const int* __restrict__ region, float* __restrict__ outf,
    __nv_bfloat16* __restrict__ out_h, __nv_bfloat16* __restrict__ out_l)
{
    constexpr int HIN  = 2 * HOUT;
    constexpr int KP   = 9 * CINP;
    constexpr int NC   = (KP + 63) / 64;
    constexpr int NT   = COUT / 8;
    constexpr int LOGH = (HOUT == 128) ? 7 : (HOUT == 64) ? 6 : 5;
    constexpr int SSB  = (2 * 128 * 72 + 2 * COUT * 72) * 2;   // stage bytes

    extern __shared__ __align__(16) char sm[];
    float* bias_s = (float*)(sm + STAGES * SSB);

    const int tid = threadIdx.x, lane = tid & 31, wid = tid >> 5;
    const int b   = blockIdx.z;
    const int px0 = blockIdx.x * 128;
    const int r   = region[b] & (R_ - 1);
    const int g   = lane >> 2, tc = lane & 3;

    for (int i = tid; i < COUT; i += 256) bias_s[i] = Bias[r * COUT + i];

    float acc[NT][4];
#pragma unroll
    for (int n = 0; n < NT; n++)
        acc[n][0] = acc[n][1] = acc[n][2] = acc[n][3] = 0.0f;

    const __nv_bfloat16* wr = wimg + (size_t)r * NC * 2 * COUT * 72;

    // ---- stage chunk c into buffer s (pure cp.async) ----
    auto stage = [&](int c, int s) {
        char* sb = sm + s * SSB;
        const u32 a_h = smem_u32(sb);
        const u32 bsm = a_h + 2 * 18432;
        const char* wsrc = (const char*)(wr + (size_t)c * 2 * COUT * 72);
        for (int i = tid; i < 2 * COUT * 9; i += 256)
            CP16(bsm + i * 16, wsrc + (size_t)i * 16);
        for (int i = tid; i < 2048; i += 256) {
            const int m = i >> 4, q = i & 15;
            const int k = c * 64 + q * 4;
            const int px = px0 + m;
            const int oy = px >> LOGH, ox = px & (HOUT - 1);
            const int tap = k >> LOGC;
            const int ci  = k & (CINP - 1);
            const int ty = tap / 3, tx2 = tap - 3 * ty;
            const int iy = 2 * oy + ty - 1, ix = 2 * ox + tx2 - 1;
            const bool valid = (tap < 9) && ((unsigned)iy < (unsigned)HIN)
                                         && ((unsigned)ix < (unsigned)HIN);
            const size_t off = valid
                ? (((size_t)(b * HIN + iy) * HIN + ix) * CINP + ci) : 0;
            const int sz = valid ? 8 : 0;
            const u32 d = a_h + m * 144 + q * 8;
            CP8Z(d,         src_h + off, sz);
            CP8Z(d + 18432, src_l + off, sz);
        }
        CP_COMMIT();
    };

    // ---- MMA chunk c from buffer s ----
    auto domma = [&](int c, int s) {
        const int rem = KP - c * 64;
        const int nks = (rem >= 64) ? 4 : ((rem + 15) >> 4);
        const char* sb = sm + s * SSB;
        const char* ah = sb + (wid * 16 + g) * 144 + tc * 4;
        const char* al = ah + 18432;
        const char* bh = sb + 2 * 18432 + g * 144 + tc * 4;
        const char* bl = bh + COUT * 144;
#pragma unroll
        for (int term = 0; term < 3; term++) {
            const char* arow = (term == 2) ? al : ah;
            const char* brow = (term == 1) ? bl : bh;
            for (int ks = 0; ks < nks; ks++) {
                const int kb = ks * 32;
                const u32 a0 = *(const u32*)(arow + kb);
                const u32 a1 = *(const u32*)(arow + 8 * 144 + kb);
                const u32 a2 = *(const u32*)(arow + kb + 16);
                const u32 a3 = *(const u32*)(arow + 8 * 144 + kb + 16);
#pragma unroll
                for (int nt = 0; nt < NT; nt++) {
                    const u32 b0 = *(const u32*)(brow + nt * 8 * 144 + kb);
                    const u32 b1 = *(const u32*)(brow + nt * 8 * 144 + kb + 16);
                    asm volatile(
                        "mma.sync.aligned.m16n8k16.row.col.f32.bf16.bf16.f32 "
                        "{%0,%1,%2,%3}, {%4,%5,%6,%7}, {%8,%9}, {%0,%1,%2,%3};"
                        : "+f"(acc[nt][0]), "+f"(acc[nt][1]),
                          "+f"(acc[nt][2]), "+f"(acc[nt][3])
                        : "r"(a0), "r"(a1), "r"(a2), "r"(a3), "r"(b0), "r"(b1));
                }
            }
        }
    };

    stage(0, 0);
    for (int c = 0; c < NC; c++) {
        if (STAGES == 2 && c + 1 < NC) stage(c + 1, (c + 1) & 1);
        if (STAGES == 2 && c + 1 < NC) { CP_WAIT1(); } else { CP_WAIT0(); }
        __syncthreads();
        domma(c, (STAGES == 2) ? (c & 1) : 0);
        __syncthreads();     // all warps done reading before buffer reuse
    }

    // ---- epilogue: bias + ReLU ----
#pragma unroll
    for (int half = 0; half < 2; half++) {
        const int m  = wid * 16 + g + half * 8;
        const int px = px0 + m;
        const int oy = px >> LOGH, ox = px & (HOUT - 1);
        const size_t base = (((size_t)b * HOUT + oy) * HOUT + ox) * COUT;
#pragma unroll
        for (int nt = 0; nt < NT; nt++) {
            const int n = nt * 8 + tc * 2;
            const float y0 = fmaxf(acc[nt][half * 2 + 0] + bias_s[n + 0], 0.0f);
            const float y1 = fmaxf(acc[nt][half * 2 + 1] + bias_s[n + 1], 0.0f);
            if (OUTF32) {
                *(float2*)(outf + base + n) = make_float2(y0, y1);
            } else {
                const __nv_bfloat16 h0 = __float2bfloat16_rn(y0);
                const __nv_bfloat16 h1 = __float2bfloat16_rn(y1);
                const __nv_bfloat16 l0 = __float2bfloat16_rn(y0 - __bfloat162float(h0));
                const __nv_bfloat16 l1 = __float2bfloat16_rn(y1 - __bfloat162float(h1));
                *(u32*)(out_h + base + n) =
                    (u32)__bfloat16_as_ushort(h0) | ((u32)__bfloat16_as_ushort(h1) << 16);
                *(u32*)(out_l + base + n) =
                    (u32)__bfloat16_as_ushort(l0) | ((u32)__bfloat16_as_ushort(l1) << 16);
            }
        }
    }
}

// ---------------------------------------------------------------------------
__global__ void __launch_bounds__(128) gap_part(const float* __restrict__ in,
                                                float* __restrict__ part)
{
    const int b = blockIdx.y, s = blockIdx.x, c = threadIdx.x;
    const float* p = in + ((size_t)b * 1024 + s * 128) * 128 + c;
    float a0 = 0, a1 = 0, a2 = 0, a3 = 0;
#pragma unroll 4
    for (int i = 0; i < 128; i += 4) {
        a0 += p[(size_t)(i + 0) * 128];
        a1 += p[(size_t)(i + 1) * 128];
        a2 += p[(size_t)(i + 2) * 128];
        a3 += p[(size_t)(i + 3) * 128];
    }
    part[(b * 8 + s) * 128 + c] = a0 + a1 + a2 + a3;
}

__global__ void __launch_bounds__(128) fc_k(const float* __restrict__ part,
                                            const float* __restrict__ fw,
                                            const float* __restrict__ fb,
                                            const int* __restrict__ region,
                                            float* __restrict__ out)
{
    __shared__ float f[128];
    const int b = blockIdx.x, tid = threadIdx.x;
    const int r = region[b] & (R_ - 1);
    float s = 0.0f;
#pragma unroll
    for (int q = 0; q < 8; q++) s += part[(b * 8 + q) * 128 + tid];
    f[tid] = s * (1.0f / 1024.0f);
    __syncthreads();
    if (tid < 32) {
        const float* w0 = fw + ((size_t)r * 2 + 0) * 128;
        const float* w1 = fw + ((size_t)r * 2 + 1) * 128;
        float p0 = 0.0f, p1 = 0.0f;
#pragma unroll
        for (int i = tid; i < 128; i += 32) {
            p0 = fmaf(f[i], w0[i], p0);
            p1 = fmaf(f[i], w1[i], p1);
        }
#pragma unroll
        for (int o = 16; o > 0; o >>= 1) {
            p0 += __shfl_down_sync(0xFFFFFFFFu, p0, o);
            p1 += __shfl_down_sync(0xFFFFFFFFu, p1, o);
        }
        if (tid == 0) {
            out[b * 2 + 0] = p0 + fb[r * 2 + 0];
            out[b * 2 + 1] = p1 + fb[r * 2 + 1];
        }
    }
}

// ---------------------------------------------------------------------------
extern "C" void kernel_launch(void* const* d_in, const int* in_sizes, int n_in,
                              void* d_out, int out_size)
{
    const float* image  = (const float*)d_in[0];
    const int*   region = (const int*)d_in[1];
    const float* w1     = (const float*)d_in[2];
    const float* b1     = (const float*)d_in[3];
    const float* w2     = (const float*)d_in[4];
    const float* b2     = (const float*)d_in[5];
    const float* w3     = (const float*)d_in[6];
    const float* b3     = (const float*)d_in[7];
    const float* fw     = (const float*)d_in[8];
    const float* fb     = (const float*)d_in[9];
    float* out = (float*)d_out;

    __nv_bfloat16 *imgh, *imgl, *b1h, *b1l, *b2h, *b2l, *w1img, *w2img, *w3img;
    float *buf3, *part;
    cudaGetSymbolAddress((void**)&imgh, g_imgh);
    cudaGetSymbolAddress((void**)&imgl, g_imgl);
    cudaGetSymbolAddress((void**)&b1h, g_b1h);
    cudaGetSymbolAddress((void**)&b1l, g_b1l);
    cudaGetSymbolAddress((void**)&b2h, g_b2h);
    cudaGetSymbolAddress((void**)&b2l, g_b2l);
    cudaGetSymbolAddress((void**)&buf3, g_buf3);
    cudaGetSymbolAddress((void**)&part, g_part);
    cudaGetSymbolAddress((void**)&w1img, g_w1img);
    cudaGetSymbolAddress((void**)&w2img, g_w2img);
    cudaGetSymbolAddress((void**)&w3img, g_w3img);

    // Preps
    prep_img<<<(B_ * 65536) / 256, 256>>>(image, imgh, imgl);
    prep_w<3, 4, 32><<<(R_ * 1 * 2 * 32 * 72 + 255) / 256, 256>>>(w1, w1img);
    prep_w<32, 32, 64><<<(R_ * 5 * 2 * 64 * 72 + 255) / 256, 256>>>(w2, w2img);
    prep_w<64, 64, 128><<<(R_ * 9 * 2 * 128 * 72 + 255) / 256, 256>>>(w3, w3img);

    // Dynamic smem: STAGES*((2*128*72 + 2*COUT*72)*2) + COUT*4
    const int SM1 = 1 * (36864 + 2 * 32 * 144) + 32 * 4;     //  46.2 KB
    const int SM2 = 2 * (36864 + 2 * 64 * 144) + 64 * 4;     // 110.8 KB
    const int SM3 = 2 * (36864 + 2 * 128 * 144) + 128 * 4;   // 148.0 KB
    cudaFuncSetAttribute(conv_mma3<4, 2, 32, 128, false, 1>,
                         cudaFuncAttributeMaxDynamicSharedMemorySize, SM1);
    cudaFuncSetAttribute(conv_mma3<32, 5, 64, 64, false, 2>,
                         cudaFuncAttributeMaxDynamicSharedMemorySize, SM2);
    cudaFuncSetAttribute(conv_mma3<64, 6, 128, 32, true, 2>,
                         cudaFuncAttributeMaxDynamicSharedMemorySize, SM3);

    // conv1: padded-4ch image planes -> bf16 hi/lo NHWC 32ch
    conv_mma3<4, 2, 32, 128, false, 1><<<dim3(128, 1, B_), 256, SM1>>>(
        imgh, imgl, w1img, b1, region, nullptr, b1h, b1l);
    // conv2
    conv_mma3<32, 5, 64, 64, false, 2><<<dim3(32, 1, B_), 256, SM2>>>(
        b1h, b1l, w2img, b2, region, nullptr, b2h, b2l);
    // conv3 -> fp32 NHWC
    conv_mma3<64, 6, 128, 32, true, 2><<<dim3(8, 1, B_), 256, SM3>>>(
        b2h, b2l, w3img, b3, region, buf3, nullptr, nullptr);

    gap_part<<<dim3(8, B_), 128>>>(buf3, part);
    fc_k<<<B_, 128>>>(part, fw, fb, region, out);
}

// round 9
// speedup vs baseline: 3.4807x; 1.0223x over previous
#include <cuda_runtime.h>
#include <cuda_bf16.h>
#include <cstdint>

// ---------------------------------------------------------------------------
// RegionModel round-9: mma.sync bf16 implicit GEMM, split-bf16 3-term fp32
// emulation (Ah*Bh + Ah*Bl + Al*Bh). NHWC bf16 hi/lo activation planes.
// New vs R8: 2-D warp tiling (WMxWN), ldmatrix.x4 fragment loads, 16B
// cp.async A-staging, 3-buffer ring with one sync per K-chunk.
// ---------------------------------------------------------------------------

#define B_ 128
#define R_ 8

typedef unsigned int u32;
typedef unsigned long long u64;
typedef unsigned short u16;

// Activations (device globals)
__device__ __align__(16) __nv_bfloat16 g_imgh[(size_t)B_ * 256 * 256 * 4];
__device__ __align__(16) __nv_bfloat16 g_imgl[(size_t)B_ * 256 * 256 * 4];
__device__ __align__(16) __nv_bfloat16 g_b1h[(size_t)B_ * 128 * 128 * 32];
__device__ __align__(16) __nv_bfloat16 g_b1l[(size_t)B_ * 128 * 128 * 32];
__device__ __align__(16) __nv_bfloat16 g_b2h[(size_t)B_ * 64 * 64 * 64];
__device__ __align__(16) __nv_bfloat16 g_b2l[(size_t)B_ * 64 * 64 * 64];
__device__ float g_buf3[(size_t)B_ * 32 * 32 * 128];
__device__ float g_part[B_ * 8 * 128];
// Weight images: [R][NC][hi|lo][COUT][72 u16], k = tap*CINP + ci, zero-padded
__device__ __align__(16) __nv_bfloat16 g_w1img[R_ * 1 * 2 * 32 * 72];
__device__ __align__(16) __nv_bfloat16 g_w2img[R_ * 5 * 2 * 64 * 72];
__device__ __align__(16) __nv_bfloat16 g_w3img[R_ * 9 * 2 * 128 * 72];

__device__ __forceinline__ u32 smem_u32(const void* p) {
    u32 a;
    asm("{ .reg .u64 t; cvta.to.shared.u64 t, %1; cvt.u32.u64 %0, t; }"
        : "=r"(a) : "l"(p));
    return a;
}
#define CP16(dst, src) \
    asm volatile("cp.async.cg.shared.global [%0], [%1], 16;" :: "r"(dst), "l"(src))
#define CP16Z(dst, src, sz) \
    asm volatile("cp.async.cg.shared.global [%0], [%1], 16, %2;" \
                 :: "r"(dst), "l"(src), "r"(sz))
#define CP8Z(dst, src, sz) \
    asm volatile("cp.async.ca.shared.global [%0], [%1], 8, %2;" \
                 :: "r"(dst), "l"(src), "r"(sz))
#define CP_COMMIT() asm volatile("cp.async.commit_group;" ::: "memory")
#define CP_WAIT0()  asm volatile("cp.async.wait_group 0;" ::: "memory")
#define CP_WAIT1()  asm volatile("cp.async.wait_group 1;" ::: "memory")
#define LDSM4(r, a) \
    asm volatile("ldmatrix.sync.aligned.m8n8.x4.shared.b16 {%0,%1,%2,%3}, [%4];" \
                 : "=r"((r)[0]), "=r"((r)[1]), "=r"((r)[2]), "=r"((r)[3]) : "r"(a))

// ---------------------------------------------------------------------------
__global__ void __launch_bounds__(256) prep_img(const float* __restrict__ img,
                                                __nv_bfloat16* __restrict__ oh,
                                                __nv_bfloat16* __restrict__ ol)
{
    const int idx = blockIdx.x * 256 + threadIdx.x;   // B*65536
    if (idx >= B_ * 65536) return;
    const int b = idx >> 16, p = idx & 65535;
    const float* ip = img + (size_t)b * 3 * 65536 + p;
    u16 h[4], l[4];
#pragma unroll
    for (int c = 0; c < 3; c++) {
        const float x = __ldg(ip + (size_t)c * 65536);
        const __nv_bfloat16 hb = __float2bfloat16_rn(x);
        h[c] = __bfloat16_as_ushort(hb);
        l[c] = __bfloat16_as_ushort(__float2bfloat16_rn(x - __bfloat162float(hb)));
    }
    h[3] = 0; l[3] = 0;
    ((u64*)oh)[idx] = *(const u64*)h;
    ((u64*)ol)[idx] = *(const u64*)l;
}

// ---------------------------------------------------------------------------
template <int CIN, int CINP, int COUT>
__global__ void __launch_bounds__(256) prep_w(const float* __restrict__ W,
                                              __nv_bfloat16* __restrict__ img)
{
    constexpr int KP = 9 * CINP;
    constexpr int NC = (KP + 63) / 64;
    const int idx = blockIdx.x * 256 + threadIdx.x;
    if (idx >= R_ * NC * 2 * COUT * 72) return;
    const int kl = idx % 72;
    int t = idx / 72;
    const int n  = t % COUT; t /= COUT;
    const int hl = t % 2;    t /= 2;
    const int c  = t % NC;
    const int r  = t / NC;

    __nv_bfloat16 ob = __float2bfloat16_rn(0.0f);
    const int k = c * 64 + kl;
    if (kl < 64 && k < KP) {
        const int tap = k / CINP, ci = k % CINP;
        if (tap < 9 && ci < CIN) {
            const float w = W[(((size_t)r * COUT + n) * CIN + ci) * 9 + tap];
            const __nv_bfloat16 h = __float2bfloat16_rn(w);
            ob = hl ? __float2bfloat16_rn(w - __bfloat162float(h)) : h;
        }
    }
    img[idx] = ob;
}

// ---------------------------------------------------------------------------
// Implicit-GEMM conv. grid = (HOUT*HOUT/128, 1, B). 256 threads, 8 warps
// in a WM x WN grid. Per stage: A hi|lo [128*72 u16 each] | B hi|lo.
// ---------------------------------------------------------------------------
template <int CINP, int LOGC, int COUT, int HOUT, int WM, int WN,
          bool OUTF32, int STAGES>
__global__ void __launch_bounds__(256) conv_mma4(
    const __nv_bfloat16* __restrict__ src_h, const __nv_bfloat16* __restrict__ src_l,
    const __nv_bfloat16* __restrict__ wimg, const float* __restrict__ Bias,
    const int* __restrict__ region, float* __restrict__ outf,
    __nv_bfloat16* __restrict__ out_h, __nv_bfloat16* __restrict__ out_l)
{
    constexpr int HIN  = 2 * HOUT;
    constexpr int KP   = 9 * CINP;
    constexpr int NC   = (KP + 63) / 64;
    constexpr int MF   = 128 / (16 * WM);     // m16 frags per warp
    constexpr int NF   = COUT / (8 * WN);     // n8 tiles per warp
    constexpr int LOGH = (HOUT == 128) ? 7 : (HOUT == 64) ? 6 : 5;
    constexpr int SSB  = 2 * 18432 + 2 * COUT * 144;

    extern __shared__ __align__(16) char sm[];
    float* bias_s = (float*)(sm + STAGES * SSB);

    const int tid = threadIdx.x, lane = tid & 31, wid = tid >> 5;
    const int b   = blockIdx.z;
    const int px0 = blockIdx.x * 128;
    const int r   = region[b] & (R_ - 1);
    const int g   = lane >> 2, tc = lane & 3;
    const int wm  = wid & (WM - 1), wn = wid / WM;
    const int M0  = wm * (128 / WM);
    const int N0  = wn * (COUT / WN);

    for (int i = tid; i < COUT; i += 256) bias_s[i] = Bias[r * COUT + i];

    float acc[MF][NF][4];
#pragma unroll
    for (int mf = 0; mf < MF; mf++)
#pragma unroll
        for (int nf = 0; nf < NF; nf++)
            acc[mf][nf][0] = acc[mf][nf][1] = acc[mf][nf][2] = acc[mf][nf][3] = 0.f;

    const __nv_bfloat16* wr = wimg + (size_t)r * NC * 2 * COUT * 72;

    // ldmatrix per-lane row offsets
    const int al_off = ((lane & 7) + ((lane >> 3) & 1) * 8) * 144 + (lane >> 4) * 16;
    const int bl_off = ((lane & 7) + ((lane >> 4) & 1) * 8) * 144 + ((lane >> 3) & 1) * 16;

    auto stage = [&](int c, int s) {
        char* sb = sm + s * SSB;
        const u32 au = smem_u32(sb);
        const u32 bu = au + 2 * 18432;
        const char* wsrc = (const char*)(wr + (size_t)c * 2 * COUT * 72);
        for (int i = tid; i < 2 * COUT * 9; i += 256)
            CP16(bu + i * 16, wsrc + (size_t)i * 16);
        if (CINP == 4) {
            // conv1: 8B ops, taps 0..8 real, q 9..11 zero pad (read by nks=3)
            for (int i = tid; i < 2048; i += 256) {
                const int m = i >> 4, q = i & 15;
                if (q >= 12) continue;
                if (q < 9) {
                    const int px = px0 + m;
                    const int oy = px >> LOGH, ox = px & (HOUT - 1);
                    const int ty = q / 3, tx2 = q - 3 * ty;
                    const int iy = 2 * oy + ty - 1, ix = 2 * ox + tx2 - 1;
                    const bool v = (unsigned)iy < (unsigned)HIN &&
                                   (unsigned)ix < (unsigned)HIN;
                    const size_t off = v ? (((size_t)(b * HIN + iy) * HIN + ix) * 4) : 0;
                    const int sz = v ? 8 : 0;
                    const u32 d = au + m * 144 + q * 8;
                    CP8Z(d, src_h + off, sz);
                    CP8Z(d + 18432, src_l + off, sz);
                } else {
                    *(u64*)(sb + m * 144 + q * 8) = 0;
                    *(u64*)(sb + 18432 + m * 144 + q * 8) = 0;
                }
            }
        } else {
            // 16B ops: 8 channels per op
            for (int i = tid; i < 1024; i += 256) {
                const int m = i >> 3, q = i & 7;
                const int k = c * 64 + q * 8;
                if (k >= KP) continue;
                const int tap = k >> LOGC, ci0 = k & (CINP - 1);
                const int ty = tap / 3, tx2 = tap - 3 * ty;
                const int px = px0 + m;
                const int oy = px >> LOGH, ox = px & (HOUT - 1);
                const int iy = 2 * oy + ty - 1, ix = 2 * ox + tx2 - 1;
                const bool v = (unsigned)iy < (unsigned)HIN &&
                               (unsigned)ix < (unsigned)HIN;
                const size_t off = v
                    ? (((size_t)(b * HIN + iy) * HIN + ix) * CINP + ci0) : 0;
                const int sz = v ? 16 : 0;
                const u32 d = au + m * 144 + q * 16;
                CP16Z(d, src_h + off, sz);
                CP16Z(d + 18432, src_l + off, sz);
            }
        }
    };

    auto domma = [&](int c, int s) {
        const int rem = KP - c * 64;
        const int nks = (rem >= 64) ? 4 : ((rem + 15) >> 4);
        const u32 au  = smem_u32(sm + s * SSB);
        const u32 Ahi = au, Alo = au + 18432;
        const u32 Bhi = au + 2 * 18432, Blo = Bhi + COUT * 144;
#pragma unroll
        for (int term = 0; term < 3; term++) {
            const u32 Ab = (term == 2) ? Alo : Ahi;
            const u32 Bb = (term == 1) ? Blo : Bhi;
#pragma unroll 4
            for (int ks = 0; ks < nks; ks++) {
                const int kb = ks * 32;
                u32 af[MF][4];
#pragma unroll
                for (int mf = 0; mf < MF; mf++)
                    LDSM4(af[mf], Ab + (M0 + mf * 16) * 144 + kb + al_off);
                u32 bf[NF / 2][4];
#pragma unroll
                for (int np = 0; np < NF / 2; np++)
                    LDSM4(bf[np], Bb + (N0 + np * 16) * 144 + kb + bl_off);
#pragma unroll
                for (int mf = 0; mf < MF; mf++)
#pragma unroll
                    for (int nf = 0; nf < NF; nf++) {
                        const u32 b0 = bf[nf >> 1][(nf & 1) ? 2 : 0];
                        const u32 b1 = bf[nf >> 1][(nf & 1) ? 3 : 1];
                        asm volatile(
                            "mma.sync.aligned.m16n8k16.row.col.f32.bf16.bf16.f32 "
                            "{%0,%1,%2,%3}, {%4,%5,%6,%7}, {%8,%9}, {%0,%1,%2,%3};"
                            : "+f"(acc[mf][nf][0]), "+f"(acc[mf][nf][1]),
                              "+f"(acc[mf][nf][2]), "+f"(acc[mf][nf][3])
                            : "r"(af[mf][0]), "r"(af[mf][1]),
                              "r"(af[mf][2]), "r"(af[mf][3]), "r"(b0), "r"(b1));
                    }
            }
        }
    };

    stage(0, 0);
    CP_COMMIT();
    for (int c = 0; c < NC; c++) {
        if (STAGES > 1 && c + 1 < NC) {
            stage(c + 1, (c + 1) % 3);
            CP_COMMIT();
            CP_WAIT1();
        } else {
            CP_WAIT0();
        }
        __syncthreads();
        domma(c, (STAGES > 1) ? (c % 3) : 0);
    }

    // ---- epilogue: bias + ReLU ----
#pragma unroll
    for (int mf = 0; mf < MF; mf++)
#pragma unroll
        for (int half = 0; half < 2; half++) {
            const int m  = M0 + mf * 16 + g + half * 8;
            const int px = px0 + m;
            const int oy = px >> LOGH, ox = px & (HOUT - 1);
            const size_t base = (((size_t)b * HOUT + oy) * HOUT + ox) * COUT;
#pragma unroll
            for (int nf = 0; nf < NF; nf++) {
                const int n = N0 + nf * 8 + tc * 2;
                const float y0 = fmaxf(acc[mf][nf][half * 2 + 0] + bias_s[n + 0], 0.f);
                const float y1 = fmaxf(acc[mf][nf][half * 2 + 1] + bias_s[n + 1], 0.f);
                if (OUTF32) {
                    *(float2*)(outf + base + n) = make_float2(y0, y1);
                } else {
                    const __nv_bfloat16 h0 = __float2bfloat16_rn(y0);
                    const __nv_bfloat16 h1 = __float2bfloat16_rn(y1);
                    const __nv_bfloat16 l0 = __float2bfloat16_rn(y0 - __bfloat162float(h0));
                    const __nv_bfloat16 l1 = __float2bfloat16_rn(y1 - __bfloat162float(h1));
                    *(u32*)(out_h + base + n) =
                        (u32)__bfloat16_as_ushort(h0) | ((u32)__bfloat16_as_ushort(h1) << 16);
                    *(u32*)(out_l + base + n) =
                        (u32)__bfloat16_as_ushort(l0) | ((u32)__bfloat16_as_ushort(l1) << 16);
                }
            }
        }
}

// ---------------------------------------------------------------------------
__global__ void __launch_bounds__(128) gap_part(const float* __restrict__ in,
                                                float* __restrict__ part)
{
    const int b = blockIdx.y, s = blockIdx.x, c = threadIdx.x;
    const float* p = in + ((size_t)b * 1024 + s * 128) * 128 + c;
    float a0 = 0, a1 = 0, a2 = 0, a3 = 0;
#pragma unroll 4
    for (int i = 0; i < 128; i += 4) {
        a0 += p[(size_t)(i + 0) * 128];
        a1 += p[(size_t)(i + 1) * 128];
        a2 += p[(size_t)(i + 2) * 128];
        a3 += p[(size_t)(i + 3) * 128];
    }
    part[(b * 8 + s) * 128 + c] = a0 + a1 + a2 + a3;
}

__global__ void __launch_bounds__(128) fc_k(const float* __restrict__ part,
                                            const float* __restrict__ fw,
                                            const float* __restrict__ fb,
                                            const int* __restrict__ region,
                                            float* __restrict__ out)
{
    __shared__ float f[128];
    const int b = blockIdx.x, tid = threadIdx.x;
    const int r = region[b] & (R_ - 1);
    float s = 0.0f;
#pragma unroll
    for (int q = 0; q < 8; q++) s += part[(b * 8 + q) * 128 + tid];
    f[tid] = s * (1.0f / 1024.0f);
    __syncthreads();
    if (tid < 32) {
        const float* w0 = fw + ((size_t)r * 2 + 0) * 128;
        const float* w1 = fw + ((size_t)r * 2 + 1) * 128;
        float p0 = 0.0f, p1 = 0.0f;
#pragma unroll
        for (int i = tid; i < 128; i += 32) {
            p0 = fmaf(f[i], w0[i], p0);
            p1 = fmaf(f[i], w1[i], p1);
        }
#pragma unroll
        for (int o = 16; o > 0; o >>= 1) {
            p0 += __shfl_down_sync(0xFFFFFFFFu, p0, o);
            p1 += __shfl_down_sync(0xFFFFFFFFu, p1, o);
        }
        if (tid == 0) {
            out[b * 2 + 0] = p0 + fb[r * 2 + 0];
            out[b * 2 + 1] = p1 + fb[r * 2 + 1];
        }
    }
}

// ---------------------------------------------------------------------------
extern "C" void kernel_launch(void* const* d_in, const int* in_sizes, int n_in,
                              void* d_out, int out_size)
{
    const float* image  = (const float*)d_in[0];
    const int*   region = (const int*)d_in[1];
    const float* w1     = (const float*)d_in[2];
    const float* b1     = (const float*)d_in[3];
    const float* w2     = (const float*)d_in[4];
    const float* b2     = (const float*)d_in[5];
    const float* w3     = (const float*)d_in[6];
    const float* b3     = (const float*)d_in[7];
    const float* fw     = (const float*)d_in[8];
    const float* fb     = (const float*)d_in[9];
    float* out = (float*)d_out;

    __nv_bfloat16 *imgh, *imgl, *b1h, *b1l, *b2h, *b2l, *w1img, *w2img, *w3img;
    float *buf3, *part;
    cudaGetSymbolAddress((void**)&imgh, g_imgh);
    cudaGetSymbolAddress((void**)&imgl, g_imgl);
    cudaGetSymbolAddress((void**)&b1h, g_b1h);
    cudaGetSymbolAddress((void**)&b1l, g_b1l);
    cudaGetSymbolAddress((void**)&b2h, g_b2h);
    cudaGetSymbolAddress((void**)&b2l, g_b2l);
    cudaGetSymbolAddress((void**)&buf3, g_buf3);
    cudaGetSymbolAddress((void**)&part, g_part);
    cudaGetSymbolAddress((void**)&w1img, g_w1img);
    cudaGetSymbolAddress((void**)&w2img, g_w2img);
    cudaGetSymbolAddress((void**)&w3img, g_w3img);

    // Preps
    prep_img<<<(B_ * 65536) / 256, 256>>>(image, imgh, imgl);
    prep_w<3, 4, 32><<<(R_ * 1 * 2 * 32 * 72 + 255) / 256, 256>>>(w1, w1img);
    prep_w<32, 32, 64><<<(R_ * 5 * 2 * 64 * 72 + 255) / 256, 256>>>(w2, w2img);
    prep_w<64, 64, 128><<<(R_ * 9 * 2 * 128 * 72 + 255) / 256, 256>>>(w3, w3img);

    // Dynamic smem: STAGES*(2*18432 + 2*COUT*144) + COUT*4
    const int SM1 = 1 * (36864 + 2 * 32 * 144) + 32 * 4;     //  46.2 KB
    const int SM2 = 3 * (36864 + 2 * 64 * 144) + 64 * 4;     // 162.3 KB
    const int SM3 = 3 * (36864 + 2 * 128 * 144) + 128 * 4;   // 216.6 KB
    cudaFuncSetAttribute(conv_mma4<4, 2, 32, 128, 8, 1, false, 1>,
                         cudaFuncAttributeMaxDynamicSharedMemorySize, SM1);
    cudaFuncSetAttribute(conv_mma4<32, 5, 64, 64, 4, 2, false, 3>,
                         cudaFuncAttributeMaxDynamicSharedMemorySize, SM2);
    cudaFuncSetAttribute(conv_mma4<64, 6, 128, 32, 2, 4, true, 3>,
                         cudaFuncAttributeMaxDynamicSharedMemorySize, SM3);

    // conv1: padded-4ch image planes -> bf16 hi/lo NHWC 32ch
    conv_mma4<4, 2, 32, 128, 8, 1, false, 1><<<dim3(128, 1, B_), 256, SM1>>>(
        imgh, imgl, w1img, b1, region, nullptr, b1h, b1l);
    // conv2
    conv_mma4<32, 5, 64, 64, 4, 2, false, 3><<<dim3(32, 1, B_), 256, SM2>>>(
        b1h, b1l, w2img, b2, region, nullptr, b2h, b2l);
    // conv3 -> fp32 NHWC
    conv_mma4<64, 6, 128, 32, 2, 4, true, 3><<<dim3(8, 1, B_), 256, SM3>>>(
        b2h, b2l, w3img, b3, region, buf3, nullptr, nullptr);

    gap_part<<<dim3(8, B_), 128>>>(buf3, part);
    fc_k<<<B_, 128>>>(part, fw, fb, region, out);
}